// round 2
// baseline (speedup 1.0000x reference)
#include <cuda_runtime.h>

// GraphAttentionPooling: B=196608 rows of F=256, pooled in groups of P=3 with
// softmax attention over a 1-unit linear scorer.
//   scores[g,p] = dot(x[g,p,:], w) + bias
//   att = softmax_p(scores)
//   out[g,:]   = sum_p att[p] * x[g,p,:]
//
// One warp per group. Each lane owns 8 features per row (2 x float4,
// coalesced: float4 indices lane and lane+32 within the 64-float4 row).
// Rows stay in registers between the score pass and the weighted-sum pass,
// so each input byte is read from DRAM exactly once. HBM-bound:
// 192 MiB read + 64 MiB write -> ~40 us floor.

constexpr int FEAT4 = 64;   // 256 floats = 64 float4 per row
constexpr int P     = 3;

__global__ __launch_bounds__(256, 8)
void gap_kernel(const float4* __restrict__ x4,
                const float4* __restrict__ w4,
                const float*  __restrict__ bias,
                float4*       __restrict__ out4,
                int G)
{
    const int warp = (blockIdx.x * blockDim.x + threadIdx.x) >> 5;
    const int lane = threadIdx.x & 31;
    if (warp >= G) return;
    const int g = warp;

    // Weight slice for this lane (L1/L2 resident, broadcast across warps)
    const float4 w0 = w4[lane];
    const float4 w1 = w4[lane + 32];

    const float4* base = x4 + (size_t)g * (P * FEAT4);

    float4 ra[P], rb[P];
    float  s[P];

    // Front-batched loads (high MLP), then partial dot products.
#pragma unroll
    for (int p = 0; p < P; ++p) {
        ra[p] = base[p * FEAT4 + lane];
        rb[p] = base[p * FEAT4 + 32 + lane];
    }
#pragma unroll
    for (int p = 0; p < P; ++p) {
        float acc = 0.0f;
        acc = fmaf(ra[p].x, w0.x, acc);
        acc = fmaf(ra[p].y, w0.y, acc);
        acc = fmaf(ra[p].z, w0.z, acc);
        acc = fmaf(ra[p].w, w0.w, acc);
        acc = fmaf(rb[p].x, w1.x, acc);
        acc = fmaf(rb[p].y, w1.y, acc);
        acc = fmaf(rb[p].z, w1.z, acc);
        acc = fmaf(rb[p].w, w1.w, acc);
        s[p] = acc;
    }

    // Three warp reductions in lockstep.
#pragma unroll
    for (int off = 16; off; off >>= 1) {
        s[0] += __shfl_xor_sync(0xffffffffu, s[0], off);
        s[1] += __shfl_xor_sync(0xffffffffu, s[1], off);
        s[2] += __shfl_xor_sync(0xffffffffu, s[2], off);
    }

    const float b = bias[0];
    s[0] += b; s[1] += b; s[2] += b;

    // 3-way softmax (numerically stable)
    const float m  = fmaxf(fmaxf(s[0], s[1]), s[2]);
    const float e0 = __expf(s[0] - m);
    const float e1 = __expf(s[1] - m);
    const float e2 = __expf(s[2] - m);
    const float inv = 1.0f / (e0 + e1 + e2);
    const float a0 = e0 * inv, a1 = e1 * inv, a2 = e2 * inv;

    // Weighted sum from registers, coalesced stores.
    float4 oa, ob;
    oa.x = fmaf(a0, ra[0].x, fmaf(a1, ra[1].x, a2 * ra[2].x));
    oa.y = fmaf(a0, ra[0].y, fmaf(a1, ra[1].y, a2 * ra[2].y));
    oa.z = fmaf(a0, ra[0].z, fmaf(a1, ra[1].z, a2 * ra[2].z));
    oa.w = fmaf(a0, ra[0].w, fmaf(a1, ra[1].w, a2 * ra[2].w));
    ob.x = fmaf(a0, rb[0].x, fmaf(a1, rb[1].x, a2 * rb[2].x));
    ob.y = fmaf(a0, rb[0].y, fmaf(a1, rb[1].y, a2 * rb[2].y));
    ob.z = fmaf(a0, rb[0].z, fmaf(a1, rb[1].z, a2 * rb[2].z));
    ob.w = fmaf(a0, rb[0].w, fmaf(a1, rb[1].w, a2 * rb[2].w));

    out4[(size_t)g * FEAT4 + lane]      = oa;
    out4[(size_t)g * FEAT4 + 32 + lane] = ob;
}

extern "C" void kernel_launch(void* const* d_in, const int* in_sizes, int n_in,
                              void* d_out, int out_size)
{
    const float* batch_rep = (const float*)d_in[0];   // [B, 256]
    const float* W_weight  = (const float*)d_in[1];   // [1, 256]
    const float* W_bias    = (const float*)d_in[2];   // [1]

    const int B = in_sizes[0] / 256;
    const int G = B / 3;

    const int threads = 256;                 // 8 warps = 8 groups / block
    const int blocks  = (G * 32 + threads - 1) / threads;

    gap_kernel<<<blocks, threads>>>((const float4*)batch_rep,
                                    (const float4*)W_weight,
                                    W_bias,
                                    (float4*)d_out,
                                    G);
}

// round 4
// speedup vs baseline: 1.0399x; 1.0399x over previous
#include <cuda_runtime.h>

// GraphAttentionPooling: B=196608 rows of F=256, pooled in groups of P=3 with
// softmax attention over a 1-unit linear scorer.
//
// Persistent grid-stride version: grid ≈ SMs * 8 CTAs, one warp walks groups
// with stride = total warps. Removes the 6.9-wave tail quantization of the
// one-warp-per-group launch. Streaming cache hints (__ldcs/__stcs) keep the
// zero-reuse x/out streams from churning L2.
// Traffic floor: 192 MiB read + 64 MiB write ≈ 37 us at ~7 TB/s.

constexpr int FEAT4 = 64;   // 256 floats = 64 float4 per row
constexpr int P     = 3;

__global__ __launch_bounds__(256)
void gap_kernel(const float4* __restrict__ x4,
                const float4* __restrict__ w4,
                const float*  __restrict__ bias,
                float4*       __restrict__ out4,
                int G)
{
    const int lane      = threadIdx.x & 31;
    const int warp0     = (blockIdx.x * blockDim.x + threadIdx.x) >> 5;
    const int warpCount = (gridDim.x * blockDim.x) >> 5;

    // Weight slice for this lane (L1-resident, broadcast across warps)
    const float4 w0 = w4[lane];
    const float4 w1 = w4[lane + 32];
    const float  b  = bias[0];

    for (int g = warp0; g < G; g += warpCount) {
        const float4* basein  = x4   + (size_t)g * (P * FEAT4);
        float4*       baseout = out4 + (size_t)g * FEAT4;

        float4 ra[P], rb[P];
        float  s[P];

        // Front-batched streaming loads (high MLP, evict-first).
#pragma unroll
        for (int p = 0; p < P; ++p) {
            ra[p] = __ldcs(basein + p * FEAT4 + lane);
            rb[p] = __ldcs(basein + p * FEAT4 + 32 + lane);
        }
#pragma unroll
        for (int p = 0; p < P; ++p) {
            float acc = 0.0f;
            acc = fmaf(ra[p].x, w0.x, acc);
            acc = fmaf(ra[p].y, w0.y, acc);
            acc = fmaf(ra[p].z, w0.z, acc);
            acc = fmaf(ra[p].w, w0.w, acc);
            acc = fmaf(rb[p].x, w1.x, acc);
            acc = fmaf(rb[p].y, w1.y, acc);
            acc = fmaf(rb[p].z, w1.z, acc);
            acc = fmaf(rb[p].w, w1.w, acc);
            s[p] = acc;
        }

        // Three warp reductions in lockstep.
#pragma unroll
        for (int off = 16; off; off >>= 1) {
            s[0] += __shfl_xor_sync(0xffffffffu, s[0], off);
            s[1] += __shfl_xor_sync(0xffffffffu, s[1], off);
            s[2] += __shfl_xor_sync(0xffffffffu, s[2], off);
        }

        // 3-way softmax (numerically stable)
        const float sb0 = s[0] + b, sb1 = s[1] + b, sb2 = s[2] + b;
        const float m  = fmaxf(fmaxf(sb0, sb1), sb2);
        const float e0 = __expf(sb0 - m);
        const float e1 = __expf(sb1 - m);
        const float e2 = __expf(sb2 - m);
        const float inv = 1.0f / (e0 + e1 + e2);
        const float a0 = e0 * inv, a1 = e1 * inv, a2 = e2 * inv;

        // Weighted sum from registers, coalesced streaming stores.
        float4 oa, ob;
        oa.x = fmaf(a0, ra[0].x, fmaf(a1, ra[1].x, a2 * ra[2].x));
        oa.y = fmaf(a0, ra[0].y, fmaf(a1, ra[1].y, a2 * ra[2].y));
        oa.z = fmaf(a0, ra[0].z, fmaf(a1, ra[1].z, a2 * ra[2].z));
        oa.w = fmaf(a0, ra[0].w, fmaf(a1, ra[1].w, a2 * ra[2].w));
        ob.x = fmaf(a0, rb[0].x, fmaf(a1, rb[1].x, a2 * rb[2].x));
        ob.y = fmaf(a0, rb[0].y, fmaf(a1, rb[1].y, a2 * rb[2].y));
        ob.z = fmaf(a0, rb[0].z, fmaf(a1, rb[1].z, a2 * rb[2].z));
        ob.w = fmaf(a0, rb[0].w, fmaf(a1, rb[1].w, a2 * rb[2].w));

        __stcs(baseout + lane,      oa);
        __stcs(baseout + 32 + lane, ob);
    }
}

extern "C" void kernel_launch(void* const* d_in, const int* in_sizes, int n_in,
                              void* d_out, int out_size)
{
    const float* batch_rep = (const float*)d_in[0];   // [B, 256]
    const float* W_weight  = (const float*)d_in[1];   // [1, 256]
    const float* W_bias    = (const float*)d_in[2];   // [1]

    const int B = in_sizes[0] / 256;
    const int G = B / 3;

    const int threads = 256;                // 8 warps/block
    // Persistent: ~8 CTAs per SM on a 148-SM part; grid-stride handles any
    // actual SM count / G. Cap at one warp per group for small inputs.
    int blocks = 148 * 8;
    const int maxBlocks = (G * 32 + threads - 1) / threads;
    if (blocks > maxBlocks) blocks = maxBlocks;

    gap_kernel<<<blocks, threads>>>((const float4*)batch_rep,
                                    (const float4*)W_weight,
                                    W_bias,
                                    (float4*)d_out,
                                    G);
}